// round 14
// baseline (speedup 1.0000x reference)
#include <cuda_runtime.h>

#define LSEQ 512
#define NH   8
#define DH   64
#define MD   512

typedef unsigned long long ull;

// ---------------- packed f32x2 helpers (sm_100+) ---------------------------
__device__ __forceinline__ ull pack2(float x, float y) {
    ull r; asm("mov.b64 %0, {%1, %2};" : "=l"(r) : "f"(x), "f"(y)); return r;
}
__device__ __forceinline__ void unpack2(ull v, float& x, float& y) {
    asm("mov.b64 {%0, %1}, %2;" : "=f"(x), "=f"(y) : "l"(v));
}
__device__ __forceinline__ void fma2(ull& d, ull a, ull b) {
    asm("fma.rn.f32x2 %0, %1, %2, %0;" : "+l"(d) : "l"(a), "l"(b));
}

// ---------------- scratch (device globals; no allocation allowed) ----------
__device__ float g_q[LSEQ * MD];                 // [l, h*64+d], pre-scaled 1/8
__device__ float g_k[LSEQ * MD];                 // [m, h*64+d]
__device__ float g_v[LSEQ * MD];                 // [m, h*64+d]
__device__ float g_attn[NH * LSEQ * LSEQ];       // fallback attn store
__device__ float g_ctx[LSEQ * MD];               // [l, h*64+d]
__device__ unsigned int g_cnt;                   // ctx completion counter

// ---------------- kernel 0: seed accumulators + reset counter --------------
__global__ void __launch_bounds__(256) init_kernel(
    const float* __restrict__ bq, const float* __restrict__ bk,
    const float* __restrict__ bv, const float* __restrict__ bo,
    float* __restrict__ out) {
    int idx = blockIdx.x * 256 + threadIdx.x;   // 0 .. 262143
    int c = idx & 511;
    g_q[idx] = bq[c] * 0.125f;
    g_k[idx] = bk[c];
    g_v[idx] = bv[c];
    out[idx] = bo[c];
    if (idx == 0) g_cnt = 0u;
}

// ---------------- 16-deep k-panel inner product, f32x2 packed --------------
__device__ __forceinline__ void mma_panel_f32x2(
    const float (*As)[64], const float (*Bs)[68],
    int tr, int tc, ull acc[4][2]) {
#pragma unroll
    for (int kk = 0; kk < 16; kk++) {
        float4 ra = *(const float4*)&As[kk][tr];
        ull b01 = *(const ull*)&Bs[kk][tc];
        ull b23 = *(const ull*)&Bs[kk][tc + 2];
        ull a0 = pack2(ra.x, ra.x);
        ull a1 = pack2(ra.y, ra.y);
        ull a2 = pack2(ra.z, ra.z);
        ull a3 = pack2(ra.w, ra.w);
        fma2(acc[0][0], a0, b01); fma2(acc[0][1], a0, b23);
        fma2(acc[1][0], a1, b01); fma2(acc[1][1], a1, b23);
        fma2(acc[2][0], a2, b01); fma2(acc[2][1], a2, b23);
        fma2(acc[3][0], a3, b01); fma2(acc[3][1], a3, b23);
    }
}

// ---------------- split-K GEMM tile body on caller smem, param depth -------
__device__ __forceinline__ void gemm_splitk_smem(
    float (*As)[64], float (*Bs)[68],
    const float* __restrict__ A, const float* __restrict__ B,
    int bm, int bn, int kbase, int kdepth, ull acc[4][2]) {
    const int tid = threadIdx.x;
    const int tr = (tid / 16) * 4;
    const int tc = (tid % 16) * 4;
    const int am = tid >> 2;
    const int ak = (tid & 3) * 4;
    const int bk = tid >> 4;
    const int bn4 = (tid & 15) * 4;

    for (int k0 = kbase; k0 < kbase + kdepth; k0 += 16) {
        float4 a = *(const float4*)(A + (bm + am) * 512 + k0 + ak);
        As[ak + 0][am] = a.x; As[ak + 1][am] = a.y;
        As[ak + 2][am] = a.z; As[ak + 3][am] = a.w;
        *(float4*)&Bs[bk][bn4] = *(const float4*)(B + (k0 + bk) * 512 + bn + bn4);
        __syncthreads();
        mma_panel_f32x2(As, Bs, tr, tc, acc);
        __syncthreads();
    }
}

__device__ __forceinline__ void atomic_epilogue(float* C, int bm, int bn,
                                                ull acc[4][2], float scale) {
    const int tid = threadIdx.x;
    const int tr = (tid / 16) * 4;
    const int tc = (tid % 16) * 4;
#pragma unroll
    for (int i = 0; i < 4; i++) {
        float c0, c1, c2, c3;
        unpack2(acc[i][0], c0, c1);
        unpack2(acc[i][1], c2, c3);
        float* row = C + (bm + tr + i) * 512 + bn + tc;
        atomicAdd(row + 0, c0 * scale);
        atomicAdd(row + 1, c1 * scale);
        atomicAdd(row + 2, c2 * scale);
        atomicAdd(row + 3, c3 * scale);
    }
}

// ---------------- kernel 1: q/k projections, split-K=8 ---------------------
// grid (8 ntile, 8 mtile, 16): z -> mat = z>>3 (0=q,1=k), ksplit = z&7
__global__ void __launch_bounds__(256) proj_qk_kernel(
    const float* __restrict__ q_in, const float* __restrict__ k_in,
    const float* __restrict__ Wq, const float* __restrict__ Wk) {
    __shared__ float As[16][64];
    __shared__ float Bs[16][68];
    const int mat = blockIdx.z >> 3;
    const int kbase = (blockIdx.z & 7) * 64;
    const int bm = blockIdx.y * 64;
    const int bn = blockIdx.x * 64;

    const float* A = mat ? k_in : q_in;
    const float* B = mat ? Wk : Wq;
    float* C = mat ? g_k : g_q;
    const float scale = mat ? 1.0f : 0.125f;

    ull acc[4][2] = {};
    gemm_splitk_smem(As, Bs, A, B, bm, bn, kbase, 64, acc);
    atomic_epilogue(C, bm, bn, acc, scale);
}

// ---------------- kernel 2: logits stream + FRONT-placed v-projection ------
// blocks [0,256): v-projection split-K=4 (wave-1 resident, hidden under stream)
// blocks [256, 256+4096): logits+softmax for (l = (bx-256)&511, h = (bx-256)>>9)
__global__ void __launch_bounds__(256) logits_merged_kernel(
    const float* __restrict__ rel_k, float* __restrict__ attn_dst,
    const float* __restrict__ v_in, const float* __restrict__ Wv) {
    __shared__ float sbuf[16 * 64 + 16 * 68];   // 2112 floats (union)
    const int tid = threadIdx.x;

    if (blockIdx.x >= 256) {
        const int bx2 = blockIdx.x - 256;
        const int l = bx2 & 511;
        const int h = bx2 >> 9;
        const int lane = tid & 31;
        const int warp = tid >> 5;
        const int li = lane & 15;
        const int gg = lane >> 4;

        float* s_logits = sbuf;           // [512]
        float* s_red  = sbuf + 512;       // [8]
        float* s_red2 = sbuf + 520;       // [8]

        const float4 q4 = *(const float4*)(g_q + l * 512 + h * 64 + li * 4);
        const float* rk_base = rel_k + ((size_t)(h * 512 + l) * 512) * 64;
        const float* k_base = g_k + h * 64;

        const int m_lo = warp * 64;
#pragma unroll 8
        for (int mi = 0; mi < 64; mi += 2) {
            const int m = m_lo + mi + gg;
            float4 r  = __ldcs((const float4*)(rk_base + (size_t)m * 64 + li * 4));
            float4 kk = *(const float4*)(k_base + (size_t)m * 512 + li * 4);
            float s = q4.x * (r.x + kk.x) + q4.y * (r.y + kk.y)
                    + q4.z * (r.z + kk.z) + q4.w * (r.w + kk.w);
#pragma unroll
            for (int o = 8; o > 0; o >>= 1) s += __shfl_xor_sync(0xffffffffu, s, o);
            if (li == 0) s_logits[m] = s;
        }
        __syncthreads();

        float v0 = s_logits[tid];
        float v1 = s_logits[tid + 256];
        float mx = fmaxf(v0, v1);
#pragma unroll
        for (int o = 16; o > 0; o >>= 1) mx = fmaxf(mx, __shfl_xor_sync(0xffffffffu, mx, o));
        if (lane == 0) s_red[warp] = mx;
        __syncthreads();
        float bmx = s_red[0];
#pragma unroll
        for (int i = 1; i < 8; i++) bmx = fmaxf(bmx, s_red[i]);

        float e0 = __expf(v0 - bmx);
        float e1 = __expf(v1 - bmx);
        float sm = e0 + e1;
#pragma unroll
        for (int o = 16; o > 0; o >>= 1) sm += __shfl_xor_sync(0xffffffffu, sm, o);
        if (lane == 0) s_red2[warp] = sm;
        __syncthreads();
        float bsum = s_red2[0];
#pragma unroll
        for (int i = 1; i < 8; i++) bsum += s_red2[i];
        const float inv = 1.0f / bsum;

        float* arow = attn_dst + (size_t)(h * 512 + l) * 512;
        arow[tid] = e0 * inv;
        arow[tid + 256] = e1 * inv;
    } else {
        // ---- v projection: g_v += v_in @ Wv (split-K=4, 128-deep) ----
        const int idx = blockIdx.x;
        const int bn = (idx & 7) * 64;
        const int bm = ((idx >> 3) & 7) * 64;
        const int kbase = (idx >> 6) * 128;

        float (*As)[64] = (float(*)[64])sbuf;
        float (*Bs)[68] = (float(*)[68])(sbuf + 16 * 64);

        ull acc[4][2] = {};
        gemm_splitk_smem(As, Bs, v_in, Wv, bm, bn, kbase, 128, acc);
        atomic_epilogue(g_v, bm, bn, acc, 1.0f);
    }
}

// ---------------- kernel 3: ctx stream + TAIL-hidden out GEMM --------------
// blocks [0,4096): ctx for (l = bx&511, h = bx>>9); release g_cnt when done.
// blocks [4096,4608): out += ctx @ Wo tile (8n,8m,8k split). Each preloads
// its 4 Wo smem panels, then acquires g_cnt==4096, then streams g_ctx.
// Deadlock-free: <=512 spinners < resident-CTA capacity, so ctx blocks
// always have slots to run regardless of dispatch order.
__global__ void __launch_bounds__(256) ctx_out_kernel(
    const float* __restrict__ rel_v, const float* __restrict__ attn_src,
    const float* __restrict__ Wo, float* __restrict__ out) {
    __shared__ float sbuf[16 * 64 + 4 * 16 * 68];   // 5376 floats (union)
    const int tid = threadIdx.x;

    if (blockIdx.x < 4096) {
        // ================= ctx = attn @ (v + rel_v) =================
        const int l = blockIdx.x & 511;
        const int h = blockIdx.x >> 9;
        const int d2 = tid & 31;
        const int mg = tid >> 5;

        float*  s_a = sbuf;                    // [512]
        float2* s_p = (float2*)(sbuf + 512);   // [256]

        const float* arow = attn_src + (size_t)(h * 512 + l) * 512;
        s_a[tid] = arow[tid];
        s_a[tid + 256] = arow[tid + 256];
        __syncthreads();

        const float2* rv = (const float2*)(rel_v + ((size_t)(h * 512 + l) * 512) * 64);
        const float2* vv = (const float2*)(g_v + h * 64);   // row stride 256 float2

        float2 acc = make_float2(0.f, 0.f);
#pragma unroll 4
        for (int m = mg; m < 512; m += 16) {
            float a0 = s_a[m];
            float a1 = s_a[m + 8];
            float2 r0 = __ldcs(rv + (size_t)m * 32 + d2);
            float2 r1 = __ldcs(rv + (size_t)(m + 8) * 32 + d2);
            float2 v0 = vv[(size_t)m * 256 + d2];
            float2 v1 = vv[(size_t)(m + 8) * 256 + d2];
            acc.x += a0 * (r0.x + v0.x) + a1 * (r1.x + v1.x);
            acc.y += a0 * (r0.y + v0.y) + a1 * (r1.y + v1.y);
        }
        s_p[tid] = acc;
        __syncthreads();
        if (tid < 32) {
            float2 r = s_p[tid];
#pragma unroll
            for (int g = 1; g < 8; g++) {
                float2 t = s_p[tid + g * 32];
                r.x += t.x; r.y += t.y;
            }
            *(float2*)(g_ctx + l * 512 + h * 64 + tid * 2) = r;
        }
        // release: make g_ctx stores visible, then bump counter
        __threadfence();
        __syncthreads();
        if (tid == 0) atomicAdd(&g_cnt, 1u);
    } else {
        // ================= out += ctx @ Wo (tail-hidden) =================
        const int idx = blockIdx.x - 4096;       // 0..511
        const int bn = (idx & 7) * 64;
        const int bm = ((idx >> 3) & 7) * 64;
        const int kbase = (idx >> 6) * 64;       // 8-way split-K, 64 deep

        float (*As)[64] = (float(*)[64])sbuf;                 // 1024 floats
        float (*Bs4)[16][68] = (float(*)[16][68])(sbuf + 1024);

        const int tr = (tid / 16) * 4;
        const int tc = (tid % 16) * 4;
        const int am = tid >> 2;
        const int ak = (tid & 3) * 4;
        const int bk = tid >> 4;
        const int bn4 = (tid & 15) * 4;

        // preload all 4 Wo panels while ctx is still running (independent data)
#pragma unroll
        for (int s = 0; s < 4; s++) {
            const int k0 = kbase + s * 16;
            *(float4*)&Bs4[s][bk][bn4] =
                *(const float4*)(Wo + (k0 + bk) * 512 + bn + bn4);
        }

        // acquire: wait for all ctx blocks
        if (tid == 0) {
            while (atomicAdd(&g_cnt, 0u) < 4096u) __nanosleep(200);
        }
        __syncthreads();

        ull acc[4][2] = {};
#pragma unroll
        for (int s = 0; s < 4; s++) {
            const int k0 = kbase + s * 16;
            float4 a = *(const float4*)(g_ctx + (bm + am) * 512 + k0 + ak);
            As[ak + 0][am] = a.x; As[ak + 1][am] = a.y;
            As[ak + 2][am] = a.z; As[ak + 3][am] = a.w;
            __syncthreads();
            mma_panel_f32x2(As, (const float(*)[68])Bs4[s], tr, tc, acc);
            __syncthreads();
        }
        atomic_epilogue(out, bm, bn, acc, 1.0f);
    }
}

// ---------------- launch ---------------------------------------------------
extern "C" void kernel_launch(void* const* d_in, const int* in_sizes, int n_in,
                              void* d_out, int out_size) {
    const float* query = (const float*)d_in[0];
    const float* key   = (const float*)d_in[1];
    const float* value = (const float*)d_in[2];
    const float* rel_k = (const float*)d_in[3];
    const float* rel_v = (const float*)d_in[4];
    const float* Wq = (const float*)d_in[5];
    const float* bq = (const float*)d_in[6];
    const float* Wk = (const float*)d_in[7];
    const float* bk = (const float*)d_in[8];
    const float* Wv = (const float*)d_in[9];
    const float* bv = (const float*)d_in[10];
    const float* Wo = (const float*)d_in[11];
    const float* bo = (const float*)d_in[12];

    float* out = (float*)d_out;
    const int OUT_ELEMS = 512 * 512;
    const int ATTN_ELEMS = 8 * 512 * 512;

    // attn goes straight into the harness output region when present;
    // otherwise into device-global scratch.
    float* attn_buf;
    if (out_size >= OUT_ELEMS + ATTN_ELEMS) {
        attn_buf = out + OUT_ELEMS;
    } else {
        static float* g_attn_addr = nullptr;
        if (!g_attn_addr) cudaGetSymbolAddress((void**)&g_attn_addr, g_attn);
        attn_buf = g_attn_addr;
    }

    init_kernel<<<OUT_ELEMS / 256, 256>>>(bq, bk, bv, bo, out);

    dim3 pg(8, 8, 16);
    proj_qk_kernel<<<pg, 256>>>(query, key, Wq, Wk);

    logits_merged_kernel<<<256 + 4096, 256>>>(rel_k, attn_buf, value, Wv);

    ctx_out_kernel<<<4096 + 512, 256>>>(rel_v, attn_buf, Wo, out);
}

// round 15
// speedup vs baseline: 1.0484x; 1.0484x over previous
#include <cuda_runtime.h>

#define LSEQ 512
#define NH   8
#define DH   64
#define MD   512

typedef unsigned long long ull;

// ---------------- packed f32x2 helpers (sm_100+) ---------------------------
__device__ __forceinline__ ull pack2(float x, float y) {
    ull r; asm("mov.b64 %0, {%1, %2};" : "=l"(r) : "f"(x), "f"(y)); return r;
}
__device__ __forceinline__ void unpack2(ull v, float& x, float& y) {
    asm("mov.b64 {%0, %1}, %2;" : "=f"(x), "=f"(y) : "l"(v));
}
__device__ __forceinline__ void fma2(ull& d, ull a, ull b) {
    asm("fma.rn.f32x2 %0, %1, %2, %0;" : "+l"(d) : "l"(a), "l"(b));
}

// ---------------- scratch (device globals; no allocation allowed) ----------
__device__ float g_q[LSEQ * MD];                 // [l, h*64+d], pre-scaled 1/8
__device__ float g_k[LSEQ * MD];                 // [m, h*64+d]
__device__ float g_v[LSEQ * MD];                 // [m, h*64+d]
__device__ float g_attn[NH * LSEQ * LSEQ];       // fallback attn store
__device__ float g_ctx[LSEQ * MD];               // [l, h*64+d]

// ---------------- kernel 0: seed accumulators ------------------------------
__global__ void __launch_bounds__(256) init_kernel(
    const float* __restrict__ bq, const float* __restrict__ bk,
    const float* __restrict__ bv, const float* __restrict__ bo,
    float* __restrict__ out) {
    // let the dependent proj grid start its (independent) GEMM immediately
    cudaTriggerProgrammaticLaunchCompletion();
    int idx = blockIdx.x * 256 + threadIdx.x;   // 0 .. 262143
    int c = idx & 511;
    g_q[idx] = bq[c] * 0.125f;
    g_k[idx] = bk[c];
    g_v[idx] = bv[c];
    out[idx] = bo[c];
}

// ---------------- 16-deep k-panel inner product, f32x2 packed --------------
__device__ __forceinline__ void mma_panel_f32x2(
    const float (*As)[64], const float (*Bs)[68],
    int tr, int tc, ull acc[4][2]) {
#pragma unroll
    for (int kk = 0; kk < 16; kk++) {
        float4 ra = *(const float4*)&As[kk][tr];
        ull b01 = *(const ull*)&Bs[kk][tc];
        ull b23 = *(const ull*)&Bs[kk][tc + 2];
        ull a0 = pack2(ra.x, ra.x);
        ull a1 = pack2(ra.y, ra.y);
        ull a2 = pack2(ra.z, ra.z);
        ull a3 = pack2(ra.w, ra.w);
        fma2(acc[0][0], a0, b01); fma2(acc[0][1], a0, b23);
        fma2(acc[1][0], a1, b01); fma2(acc[1][1], a1, b23);
        fma2(acc[2][0], a2, b01); fma2(acc[2][1], a2, b23);
        fma2(acc[3][0], a3, b01); fma2(acc[3][1], a3, b23);
    }
}

// ---------------- split-K GEMM tile body on caller smem, param depth -------
__device__ __forceinline__ void gemm_splitk_smem(
    float (*As)[64], float (*Bs)[68],
    const float* __restrict__ A, const float* __restrict__ B,
    int bm, int bn, int kbase, int kdepth, ull acc[4][2]) {
    const int tid = threadIdx.x;
    const int tr = (tid / 16) * 4;
    const int tc = (tid % 16) * 4;
    const int am = tid >> 2;
    const int ak = (tid & 3) * 4;
    const int bk = tid >> 4;
    const int bn4 = (tid & 15) * 4;

    for (int k0 = kbase; k0 < kbase + kdepth; k0 += 16) {
        float4 a = *(const float4*)(A + (bm + am) * 512 + k0 + ak);
        As[ak + 0][am] = a.x; As[ak + 1][am] = a.y;
        As[ak + 2][am] = a.z; As[ak + 3][am] = a.w;
        *(float4*)&Bs[bk][bn4] = *(const float4*)(B + (k0 + bk) * 512 + bn + bn4);
        __syncthreads();
        mma_panel_f32x2(As, Bs, tr, tc, acc);
        __syncthreads();
    }
}

__device__ __forceinline__ void atomic_epilogue(float* C, int bm, int bn,
                                                ull acc[4][2], float scale) {
    const int tid = threadIdx.x;
    const int tr = (tid / 16) * 4;
    const int tc = (tid % 16) * 4;
#pragma unroll
    for (int i = 0; i < 4; i++) {
        float c0, c1, c2, c3;
        unpack2(acc[i][0], c0, c1);
        unpack2(acc[i][1], c2, c3);
        float* row = C + (bm + tr + i) * 512 + bn + tc;
        atomicAdd(row + 0, c0 * scale);
        atomicAdd(row + 1, c1 * scale);
        atomicAdd(row + 2, c2 * scale);
        atomicAdd(row + 3, c3 * scale);
    }
}

// ---------------- kernel 1: q/k projections, split-K=8, PDL-overlapped -----
// grid (8 ntile, 8 mtile, 16): z -> mat = z>>3 (0=q,1=k), ksplit = z&7
// GEMM reads only harness inputs -> runs concurrently with init; the
// grid-dependency sync is deferred to just before the bias-accumulate.
__global__ void __launch_bounds__(256) proj_qk_kernel(
    const float* __restrict__ q_in, const float* __restrict__ k_in,
    const float* __restrict__ Wq, const float* __restrict__ Wk) {
    cudaTriggerProgrammaticLaunchCompletion();   // let logits grid stage early
    __shared__ float As[16][64];
    __shared__ float Bs[16][68];
    const int mat = blockIdx.z >> 3;
    const int kbase = (blockIdx.z & 7) * 64;
    const int bm = blockIdx.y * 64;
    const int bn = blockIdx.x * 64;

    const float* A = mat ? k_in : q_in;
    const float* B = mat ? Wk : Wq;
    float* C = mat ? g_k : g_q;
    const float scale = mat ? 1.0f : 0.125f;

    ull acc[4][2] = {};
    gemm_splitk_smem(As, Bs, A, B, bm, bn, kbase, 64, acc);

    cudaGridDependencySynchronize();             // init must have seeded C
    atomic_epilogue(C, bm, bn, acc, scale);
}

// ---------------- kernel 2: logits stream + FRONT-placed v-projection ------
// blocks [0,256): v-projection split-K=4 (wave-1 resident, hidden under stream)
// blocks [256, 256+4096): logits+softmax for (l = (bx-256)&511, h = (bx-256)>>9)
__global__ void __launch_bounds__(256) logits_merged_kernel(
    const float* __restrict__ rel_k, float* __restrict__ attn_dst,
    const float* __restrict__ v_in, const float* __restrict__ Wv) {
    __shared__ float sbuf[16 * 64 + 16 * 68];   // 2112 floats (union)
    const int tid = threadIdx.x;

    if (blockIdx.x >= 256) {
        cudaGridDependencySynchronize();        // needs g_q / g_k from proj
        const int bx2 = blockIdx.x - 256;
        const int l = bx2 & 511;
        const int h = bx2 >> 9;
        const int lane = tid & 31;
        const int warp = tid >> 5;
        const int li = lane & 15;
        const int gg = lane >> 4;

        float* s_logits = sbuf;           // [512]
        float* s_red  = sbuf + 512;       // [8]
        float* s_red2 = sbuf + 520;       // [8]

        const float4 q4 = *(const float4*)(g_q + l * 512 + h * 64 + li * 4);
        const float* rk_base = rel_k + ((size_t)(h * 512 + l) * 512) * 64;
        const float* k_base = g_k + h * 64;

        const int m_lo = warp * 64;
#pragma unroll 8
        for (int mi = 0; mi < 64; mi += 2) {
            const int m = m_lo + mi + gg;
            float4 r  = __ldcs((const float4*)(rk_base + (size_t)m * 64 + li * 4));
            float4 kk = *(const float4*)(k_base + (size_t)m * 512 + li * 4);
            float s = q4.x * (r.x + kk.x) + q4.y * (r.y + kk.y)
                    + q4.z * (r.z + kk.z) + q4.w * (r.w + kk.w);
#pragma unroll
            for (int o = 8; o > 0; o >>= 1) s += __shfl_xor_sync(0xffffffffu, s, o);
            if (li == 0) s_logits[m] = s;
        }
        __syncthreads();

        float v0 = s_logits[tid];
        float v1 = s_logits[tid + 256];
        float mx = fmaxf(v0, v1);
#pragma unroll
        for (int o = 16; o > 0; o >>= 1) mx = fmaxf(mx, __shfl_xor_sync(0xffffffffu, mx, o));
        if (lane == 0) s_red[warp] = mx;
        __syncthreads();
        float bmx = s_red[0];
#pragma unroll
        for (int i = 1; i < 8; i++) bmx = fmaxf(bmx, s_red[i]);

        float e0 = __expf(v0 - bmx);
        float e1 = __expf(v1 - bmx);
        float sm = e0 + e1;
#pragma unroll
        for (int o = 16; o > 0; o >>= 1) sm += __shfl_xor_sync(0xffffffffu, sm, o);
        if (lane == 0) s_red2[warp] = sm;
        __syncthreads();
        float bsum = s_red2[0];
#pragma unroll
        for (int i = 1; i < 8; i++) bsum += s_red2[i];
        const float inv = 1.0f / bsum;

        float* arow = attn_dst + (size_t)(h * 512 + l) * 512;
        arow[tid] = e0 * inv;
        arow[tid + 256] = e1 * inv;
    } else {
        // ---- v projection: g_v += v_in @ Wv (split-K=4, 128-deep) ----
        // GEMM reads only harness inputs -> overlap with proj; sync only
        // before the accumulate into init-seeded g_v.
        const int idx = blockIdx.x;
        const int bn = (idx & 7) * 64;
        const int bm = ((idx >> 3) & 7) * 64;
        const int kbase = (idx >> 6) * 128;

        float (*As)[64] = (float(*)[64])sbuf;
        float (*Bs)[68] = (float(*)[68])(sbuf + 16 * 64);

        ull acc[4][2] = {};
        gemm_splitk_smem(As, Bs, v_in, Wv, bm, bn, kbase, 128, acc);
        cudaGridDependencySynchronize();
        atomic_epilogue(g_v, bm, bn, acc, 1.0f);
    }
}

// ---------------- kernel 3: FUSED ctx = attn @ (v + rel_v) -----------------
// one block per (l, h); thread = (m-group 0..7, float2-d 0..31).
__global__ void __launch_bounds__(256) ctx_kernel(
    const float* __restrict__ rel_v, const float* __restrict__ attn_src) {
    cudaGridDependencySynchronize();             // needs attn + g_v
    const int l = blockIdx.x;
    const int h = blockIdx.y;
    const int tid = threadIdx.x;
    const int d2 = tid & 31;
    const int mg = tid >> 5;

    __shared__ float  s_a[512];
    __shared__ float2 s_p[256];

    const float* arow = attn_src + (size_t)(h * 512 + l) * 512;
    s_a[tid] = arow[tid];
    s_a[tid + 256] = arow[tid + 256];
    __syncthreads();

    const float2* rv = (const float2*)(rel_v + ((size_t)(h * 512 + l) * 512) * 64);
    const float2* vv = (const float2*)(g_v + h * 64);   // row stride 256 float2

    float2 acc = make_float2(0.f, 0.f);
#pragma unroll 4
    for (int m = mg; m < 512; m += 16) {
        float a0 = s_a[m];
        float a1 = s_a[m + 8];
        float2 r0 = __ldcs(rv + (size_t)m * 32 + d2);
        float2 r1 = __ldcs(rv + (size_t)(m + 8) * 32 + d2);
        float2 v0 = vv[(size_t)m * 256 + d2];
        float2 v1 = vv[(size_t)(m + 8) * 256 + d2];
        acc.x += a0 * (r0.x + v0.x) + a1 * (r1.x + v1.x);
        acc.y += a0 * (r0.y + v0.y) + a1 * (r1.y + v1.y);
    }
    s_p[tid] = acc;
    __syncthreads();
    if (tid < 32) {
        float2 r = s_p[tid];
#pragma unroll
        for (int g = 1; g < 8; g++) {
            float2 t = s_p[tid + g * 32];
            r.x += t.x; r.y += t.y;
        }
        *(float2*)(g_ctx + l * 512 + h * 64 + tid * 2) = r;
    }
}

// ---------------- kernel 4: out += ctx @ Wo (split-K=8, Wo prefetched) -----
// grid (8 ntile, 8 mtile, 8 ksplit). Wo panels are loaded to smem BEFORE the
// grid-dependency sync (independent of ctx), hiding their latency under the
// ctx tail via PDL.
__global__ void __launch_bounds__(256) out_gemm_kernel(
    const float* __restrict__ Wo, float* __restrict__ out) {
    __shared__ float As[16][64];
    __shared__ float Bs4[4][16][68];
    const int tid = threadIdx.x;
    const int bm = blockIdx.y * 64;
    const int bn = blockIdx.x * 64;
    const int kbase = blockIdx.z * 64;

    const int tr = (tid / 16) * 4;
    const int tc = (tid % 16) * 4;
    const int am = tid >> 2;
    const int ak = (tid & 3) * 4;
    const int bk = tid >> 4;
    const int bn4 = (tid & 15) * 4;

    // prefetch Wo (independent of ctx) before the dependency sync
#pragma unroll
    for (int s = 0; s < 4; s++) {
        const int k0 = kbase + s * 16;
        *(float4*)&Bs4[s][bk][bn4] =
            *(const float4*)(Wo + (k0 + bk) * 512 + bn + bn4);
    }

    cudaGridDependencySynchronize();             // g_ctx must be complete
    __syncthreads();

    ull acc[4][2] = {};
#pragma unroll
    for (int s = 0; s < 4; s++) {
        const int k0 = kbase + s * 16;
        float4 a = *(const float4*)(g_ctx + (bm + am) * 512 + k0 + ak);
        As[ak + 0][am] = a.x; As[ak + 1][am] = a.y;
        As[ak + 2][am] = a.z; As[ak + 3][am] = a.w;
        __syncthreads();
        mma_panel_f32x2(As, (const float(*)[68])Bs4[s], tr, tc, acc);
        __syncthreads();
    }
    atomic_epilogue(out, bm, bn, acc, 1.0f);
}

// ---------------- launch ---------------------------------------------------
static inline void launch_pdl(void* fn, dim3 grid, void** args) {
    cudaLaunchConfig_t cfg = {};
    cudaLaunchAttribute attrs[1];
    attrs[0].id = cudaLaunchAttributeProgrammaticStreamSerialization;
    attrs[0].val.programmaticStreamSerializationAllowed = 1;
    cfg.gridDim = grid;
    cfg.blockDim = dim3(256, 1, 1);
    cfg.dynamicSmemBytes = 0;
    cfg.stream = 0;
    cfg.attrs = attrs;
    cfg.numAttrs = 1;
    cudaLaunchKernelExC(&cfg, fn, args);
}

extern "C" void kernel_launch(void* const* d_in, const int* in_sizes, int n_in,
                              void* d_out, int out_size) {
    const float* query = (const float*)d_in[0];
    const float* key   = (const float*)d_in[1];
    const float* value = (const float*)d_in[2];
    const float* rel_k = (const float*)d_in[3];
    const float* rel_v = (const float*)d_in[4];
    const float* Wq = (const float*)d_in[5];
    const float* bq = (const float*)d_in[6];
    const float* Wk = (const float*)d_in[7];
    const float* bk = (const float*)d_in[8];
    const float* Wv = (const float*)d_in[9];
    const float* bv = (const float*)d_in[10];
    const float* Wo = (const float*)d_in[11];
    const float* bo = (const float*)d_in[12];

    float* out = (float*)d_out;
    const int OUT_ELEMS = 512 * 512;
    const int ATTN_ELEMS = 8 * 512 * 512;

    // attn goes straight into the harness output region when present;
    // otherwise into device-global scratch.
    float* attn_buf;
    if (out_size >= OUT_ELEMS + ATTN_ELEMS) {
        attn_buf = out + OUT_ELEMS;
    } else {
        static float* g_attn_addr = nullptr;
        if (!g_attn_addr) cudaGetSymbolAddress((void**)&g_attn_addr, g_attn);
        attn_buf = g_attn_addr;
    }

    init_kernel<<<OUT_ELEMS / 256, 256>>>(bq, bk, bv, bo, out);

    {
        void* args[] = {(void*)&query, (void*)&key, (void*)&Wq, (void*)&Wk};
        launch_pdl((void*)proj_qk_kernel, dim3(8, 8, 16), args);
    }
    {
        void* args[] = {(void*)&rel_k, (void*)&attn_buf, (void*)&value, (void*)&Wv};
        launch_pdl((void*)logits_merged_kernel, dim3(256 + 4096, 1, 1), args);
    }
    {
        void* args[] = {(void*)&rel_v, (void*)&attn_buf};
        launch_pdl((void*)ctx_kernel, dim3(512, 8, 1), args);
    }
    {
        void* args[] = {(void*)&Wo, (void*)&out};
        launch_pdl((void*)out_gemm_kernel, dim3(8, 8, 8), args);
    }
}